// round 1
// baseline (speedup 1.0000x reference)
#include <cuda_runtime.h>
#include <cuda_bf16.h>
#include <cstdint>

// One-hot expansion: mask [B,1,X,Y,Z] (fp32 integer labels 0..40)
//   -> out [B,40,X,Y,Z], out[:,c] = (mask == c+1) ? 1.0f : 0.0f
//
// Store-bandwidth-bound. Each thread loads one float4 of the mask (16 B) and
// writes 40 float4 results (640 B), one per label channel. Mask read traffic
// is therefore 12.6 MB total; write traffic 503 MB of fully-coalesced
// 128B-line streaming stores.

#define N_LABELS 40

__global__ __launch_bounds__(256)
void onehot40_kernel(const float4* __restrict__ mask4,
                     float4* __restrict__ out4,
                     int vol4) {
    int i = blockIdx.x * blockDim.x + threadIdx.x;
    if (i >= vol4) return;

    float4 m = mask4[i];

#pragma unroll
    for (int c = 0; c < N_LABELS; c++) {
        const float lab = (float)(c + 1);
        float4 r;
        r.x = (m.x == lab) ? 1.0f : 0.0f;
        r.y = (m.y == lab) ? 1.0f : 0.0f;
        r.z = (m.z == lab) ? 1.0f : 0.0f;
        r.w = (m.w == lab) ? 1.0f : 0.0f;
        out4[(size_t)c * (size_t)vol4 + (size_t)i] = r;
    }
}

extern "C" void kernel_launch(void* const* d_in, const int* in_sizes, int n_in,
                              void* d_out, int out_size) {
    const float* mask = (const float*)d_in[0];
    float* out = (float*)d_out;

    int vol = in_sizes[0];          // 256*256*48 = 3,145,728 (divisible by 4)
    int vol4 = vol / 4;             // 786,432

    int threads = 256;
    int blocks = (vol4 + threads - 1) / threads;

    onehot40_kernel<<<blocks, threads>>>(
        (const float4*)mask, (float4*)out, vol4);
}